// round 7
// baseline (speedup 1.0000x reference)
#include <cuda_runtime.h>

#define NB 512
#define NT 1024
#define NK 48
#define SSTART 46
#define SEND 47
#define NEGV (-10000.0f)
#define L2E 1.4426950408889634f
#define LN2F 0.6931471805599453f

// dyn smem: bp[NT*NK] u8 | e[2][NK] f32 | v[2][NK] f32 | s0[2] | red[2*NK]
#define OFF_E   (NT*NK)
#define OFF_V   (OFF_E + 2*NK*4)
#define OFF_S0  (OFF_V + 2*NK*4)
#define OFF_RED (OFF_S0 + 16)
#define SMEM_BYTES (OFF_RED + 2*NK*4)

#define PD 4   // feats prefetch pipeline depth (steps)

__device__ __forceinline__ float ex2f(float x){ float y; asm("ex2.approx.ftz.f32 %0, %1;":"=f"(y):"f"(x)); return y; }
__device__ __forceinline__ float lg2f(float x){ float y; asm("lg2.approx.f32 %0, %1;":"=f"(y):"f"(x)); return y; }
__device__ __forceinline__ unsigned long long ffma2(unsigned long long a, unsigned long long b, unsigned long long c){
    unsigned long long d; asm("fma.rn.f32x2 %0, %1, %2, %3;" : "=l"(d) : "l"(a), "l"(b), "l"(c)); return d;
}
__device__ __forceinline__ unsigned long long fadd2(unsigned long long a, unsigned long long b){
    unsigned long long d; asm("add.rn.f32x2 %0, %1, %2;" : "=l"(d) : "l"(a), "l"(b)); return d;
}
__device__ __forceinline__ unsigned long long pk2(float lo, float hi){
    unsigned long long d; asm("mov.b64 %0, {%1, %2};" : "=l"(d) : "f"(lo), "f"(hi)); return d;
}
__device__ __forceinline__ void upk2(unsigned long long v, float& lo, float& hi){
    asm("mov.b64 {%0, %1}, %2;" : "=f"(lo), "=f"(hi) : "l"(v));
}

__global__ __launch_bounds__(128, 4)
void crf_kernel(const float* __restrict__ feats,
                const float* __restrict__ trans,
                float* __restrict__ out)
{
    extern __shared__ char smc[];
    unsigned char* bp = (unsigned char*)smc;
    float* eB  = (float*)(smc + OFF_E);    // exp2 of normalized log2-alpha, dbl-buffered
    float* vB  = (float*)(smc + OFF_V);    // viterbi values (plain), dbl-buffered
    float* s0B = (float*)(smc + OFF_S0);   // broadcast normalized A[0] (shift)
    float* red = (float*)(smc + OFF_RED);  // final reduction terms

    const int b   = blockIdx.x;
    const int tid = threadIdx.x;
    // role rotation: co-resident CTAs (bids differ by 148, (>>2)&1 flips) put their
    // heavy viterbi warps on alternating SMSP pairs -> per-SMSP fwd/vit mix
    const int rot  = (b >> 2) & 1;
    const bool isF = ((tid < 64) ? 1 : 0) ^ rot;
    const int  j   = tid & 63;             // state index within role group
    const bool act = (j < NK);
    const float* f = feats + (size_t)b * NT * NK;

    // fwd: packed exp2(trans*log2e) row;  vit: packed plain trans row
    unsigned long long tp[NK/2];
    float A = 0.f, Csum = 0.f, vj = 0.f;

    if (act) {
        #pragma unroll
        for (int c = 0; c < NK/2; ++c) {
            float t0 = trans[j*NK + 2*c];
            float t1 = trans[j*NK + 2*c + 1];
            if (j == SSTART)   { t0 = NEGV; t1 = NEGV; }   // no transition into START row
            if (2*c   == SEND)   t0 = NEGV;                // no transition out of END col
            if (2*c+1 == SEND)   t1 = NEGV;
            if (isF) tp[c] = pk2(ex2f(t0 * L2E), ex2f(t1 * L2E));  // masked -> exact 0
            else     tp[c] = pk2(t0, t1);
        }
        if (isF) {
            A = (j == SSTART) ? 0.f : NEGV * L2E;
            eB[j] = (j == SSTART) ? 1.f : 0.f;
        } else {
            vj = (j == SSTART) ? 0.f : NEGV;
            vB[j] = vj;
        }
    }
    // feats register pipeline, depth PD
    float fq[PD];
    if (act) {
        #pragma unroll
        for (int i = 0; i < PD; ++i) fq[i] = __ldg(f + i*NK + j);
    }
    if (tid == 0) s0B[0] = 0.f;
    __syncthreads();

    #pragma unroll 1
    for (int g = 0; g < NT/PD; ++g) {
        #pragma unroll
        for (int u = 0; u < PD; ++u) {
            const int t  = g*PD + u;
            const int cb = u & 1;            // buffer parity (t even -> 0)
            const int nb = cb ^ 1;
            if (act) {
                const float featv = fq[u];                 // loaded PD steps ago
                float nf = 0.f;
                if (t + PD < NT) nf = __ldg(f + (t+PD)*NK + j);   // deep prefetch
                if (isF) {
                    // forward: s_j = sum_p E[j][p]*e[p]  (24 packed f32x2 FFMA)
                    const ulonglong2* e2p = (const ulonglong2*)(eB + cb*NK);
                    unsigned long long acc0 = 0ull, acc1 = 0ull;
                    #pragma unroll
                    for (int c = 0; c < NK/4; ++c) {
                        ulonglong2 ev = e2p[c];            // broadcast LDS.128
                        acc0 = ffma2(tp[2*c    ], ev.x, acc0);
                        acc1 = ffma2(tp[2*c + 1], ev.y, acc1);
                    }
                    float a0l,a0h,a1l,a1h;
                    upk2(acc0, a0l, a0h); upk2(acc1, a1l, a1h);
                    float s = (a0l + a0h) + (a1l + a1h);
                    float d = s0B[cb];                     // prev step's NORMALIZED A[0]
                    d = fminf(fmaxf(d, -200.f), 200.f);    // defensive; algebra exact
                    float raw = lg2f(s) + featv * L2E;
                    Csum += d;
                    A = raw - d;
                    eB[nb*NK + j] = ex2f(A);
                    if (j == 0) s0B[nb] = A;
                } else {
                    // viterbi: plain float, identical op order to reference -> bit-exact
                    const ulonglong2* v2p = (const ulonglong2*)(vB + cb*NK);
                    float m0=-3.4e38f, m1=-3.4e38f, m2=-3.4e38f, m3=-3.4e38f;
                    int   i0=0, i1=1, i2=2, i3=3;
                    #pragma unroll
                    for (int c = 0; c < NK/4; ++c) {
                        ulonglong2 vv = v2p[c];            // broadcast LDS.128
                        unsigned long long y01 = fadd2(vv.x, tp[2*c]);   // 2 IEEE RN adds
                        unsigned long long y23 = fadd2(vv.y, tp[2*c+1]);
                        float y0,y1,y2,y3;
                        upk2(y01, y0, y1); upk2(y23, y2, y3);
                        if (y0 > m0) { m0=y0; i0=4*c+0; }
                        if (y1 > m1) { m1=y1; i1=4*c+1; }
                        if (y2 > m2) { m2=y2; i2=4*c+2; }
                        if (y3 > m3) { m3=y3; i3=4*c+3; }
                    }
                    // merge with first-max tie-break (matches jnp.argmax)
                    float bm = m0; int bi = i0;
                    if (m1 > bm || (m1 == bm && i1 < bi)) { bm=m1; bi=i1; }
                    if (m2 > bm || (m2 == bm && i2 < bi)) { bm=m2; bi=i2; }
                    if (m3 > bm || (m3 == bm && i3 < bi)) { bm=m3; bi=i3; }
                    vj = bm + featv;                       // emission added AFTER max
                    bp[t*NK + j] = (unsigned char)bi;
                    vB[nb*NK + j] = vj;
                }
                fq[u] = nf;
            }
            __syncthreads();
        }
    }

    // ---- termination ----
    if (act) {
        float te = trans[SEND*NK + j];
        if (j == SEND) te = NEGV;                    // column END masked
        if (isF) red[j]      = A  + te * L2E;        // log2 domain (C added at end)
        else     red[NK + j] = vj + te;              // plain, bit-exact
    }
    __syncthreads();

    if (isF && j == 0) {
        // logz = logsumexp(alpha + trans[END])
        float m = -3.4e38f;
        #pragma unroll
        for (int p = 0; p < NK; ++p) m = fmaxf(m, red[p]);
        float s = 0.f;
        #pragma unroll
        for (int p = 0; p < NK; ++p) s += ex2f(red[p] - m);
        out[b] = (m + lg2f(s) + Csum) * LN2F;
    }
    if (!isF && j == 0) {
        // terminal first-max argmax + smem backtrace
        float bm = -3.4e38f; int last = 0;
        #pragma unroll
        for (int p = 0; p < NK; ++p) {
            float y = red[NK + p];
            if (y > bm) { bm = y; last = p; }
        }
        out[NB + b] = bm;
        float* po = out + 2*NB + (size_t)b * NT;
        int tag = last;
        #pragma unroll 1
        for (int t = NT - 1; t >= 0; --t) {
            po[t] = (float)tag;
            tag = bp[t*NK + tag];
        }
    }
}

extern "C" void kernel_launch(void* const* d_in, const int* in_sizes, int n_in,
                              void* d_out, int out_size)
{
    const float* feats = (const float*)d_in[0];
    const float* trans = (const float*)d_in[1];
    float* out = (float*)d_out;
    // Max dynamic smem AND full shared-memory carveout: without the carveout hint
    // the L1/shared split defaults small and caps residency at 2 CTAs/SM.
    cudaFuncSetAttribute(crf_kernel, cudaFuncAttributeMaxDynamicSharedMemorySize,
                         SMEM_BYTES);
    cudaFuncSetAttribute(crf_kernel, cudaFuncAttributePreferredSharedMemoryCarveout,
                         100);
    crf_kernel<<<NB, 128, SMEM_BYTES>>>(feats, trans, out);
}

// round 8
// speedup vs baseline: 1.1895x; 1.1895x over previous
#include <cuda_runtime.h>

#define NB 512
#define NT 1024
#define NK 48
#define SSTART 46
#define SEND 47
#define NEGV (-10000.0f)
#define L2E 1.4426950408889634f
#define LN2F 0.6931471805599453f

// dyn smem: bp[NT*NK] u8 | e[2][NK] f32 | v[2][NK] f32 | s0[2] | red[NK]
#define OFF_E   (NT*NK)
#define OFF_V   (OFF_E + 2*NK*4)
#define OFF_S0  (OFF_V + 2*NK*4)
#define OFF_RED (OFF_S0 + 16)
#define SMEM_BYTES (OFF_RED + NK*4)

#define PD 2   // feats prefetch pipeline depth (steps)

__device__ __forceinline__ float ex2f(float x){ float y; asm("ex2.approx.ftz.f32 %0, %1;":"=f"(y):"f"(x)); return y; }
__device__ __forceinline__ float lg2f(float x){ float y; asm("lg2.approx.f32 %0, %1;":"=f"(y):"f"(x)); return y; }
__device__ __forceinline__ unsigned long long ffma2(unsigned long long a, unsigned long long b, unsigned long long c){
    unsigned long long d; asm("fma.rn.f32x2 %0, %1, %2, %3;" : "=l"(d) : "l"(a), "l"(b), "l"(c)); return d;
}
__device__ __forceinline__ unsigned long long fadd2(unsigned long long a, unsigned long long b){
    unsigned long long d; asm("add.rn.f32x2 %0, %1, %2;" : "=l"(d) : "l"(a), "l"(b)); return d;
}
__device__ __forceinline__ unsigned long long pk2(float lo, float hi){
    unsigned long long d; asm("mov.b64 %0, {%1, %2};" : "=l"(d) : "f"(lo), "f"(hi)); return d;
}
__device__ __forceinline__ void upk2(unsigned long long v, float& lo, float& hi){
    asm("mov.b64 {%0, %1}, %2;" : "=f"(lo), "=f"(hi) : "l"(v));
}

__global__ __launch_bounds__(64, 4)
void crf_kernel(const float* __restrict__ feats,
                const float* __restrict__ trans,
                float* __restrict__ out)
{
    extern __shared__ char smc[];
    unsigned char* bp = (unsigned char*)smc;
    float* eB  = (float*)(smc + OFF_E);    // exp2 of normalized log2-alpha, dbl-buffered
    float* vB  = (float*)(smc + OFF_V);    // viterbi values (plain), dbl-buffered
    float* s0B = (float*)(smc + OFF_S0);   // broadcast normalized A[0] (shift)
    float* red = (float*)(smc + OFF_RED);  // final viterbi reduction terms

    const int b   = blockIdx.x;
    const int j   = threadIdx.x;           // state index; every warp identical role mix
    const bool act = (j < NK);
    const float* f = feats + (size_t)b * NT * NK;

    unsigned long long tpE[NK/2];          // packed exp2(trans*log2e) row  (forward)
    unsigned long long tpW[NK/2];          // packed plain trans row        (viterbi)
    float A = 0.f, Csum = 0.f, vj = 0.f;

    if (act) {
        #pragma unroll
        for (int c = 0; c < NK/2; ++c) {
            float t0 = trans[j*NK + 2*c];
            float t1 = trans[j*NK + 2*c + 1];
            if (j == SSTART)   { t0 = NEGV; t1 = NEGV; }   // no transition into START row
            if (2*c   == SEND)   t0 = NEGV;                // no transition out of END col
            if (2*c+1 == SEND)   t1 = NEGV;
            tpE[c] = pk2(ex2f(t0 * L2E), ex2f(t1 * L2E));  // masked -> exact 0
            tpW[c] = pk2(t0, t1);
        }
        A  = (j == SSTART) ? 0.f : NEGV * L2E;
        eB[j] = (j == SSTART) ? 1.f : 0.f;
        vj = (j == SSTART) ? 0.f : NEGV;
        vB[j] = vj;
    }
    float fq[PD];
    if (act) {
        #pragma unroll
        for (int i = 0; i < PD; ++i) fq[i] = __ldg(f + i*NK + j);
    }
    if (j == 0) s0B[0] = 0.f;
    __syncthreads();

    #pragma unroll 1
    for (int g = 0; g < NT/PD; ++g) {
        #pragma unroll
        for (int u = 0; u < PD; ++u) {
            const int t  = g*PD + u;
            const int cb = u & 1;            // buffer parity (PD even -> t parity)
            const int nb = cb ^ 1;
            if (act) {
                const float featv = fq[u];
                float nf = 0.f;
                if (t + PD < NT) nf = __ldg(f + (t+PD)*NK + j);   // prefetch

                // ---- forward: s_j = sum_p E[j][p]*e[p] (24 packed FFMA) ----
                const ulonglong2* e2p = (const ulonglong2*)(eB + cb*NK);
                unsigned long long acc0 = 0ull, acc1 = 0ull;
                #pragma unroll
                for (int c = 0; c < NK/4; ++c) {
                    ulonglong2 ev = e2p[c];                // broadcast LDS.128
                    acc0 = ffma2(tpE[2*c    ], ev.x, acc0);
                    acc1 = ffma2(tpE[2*c + 1], ev.y, acc1);
                }
                float a0l,a0h,a1l,a1h;
                upk2(acc0, a0l, a0h); upk2(acc1, a1l, a1h);
                float s = (a0l + a0h) + (a1l + a1h);
                float d = s0B[cb];                         // prev step's normalized A[0]
                d = fminf(fmaxf(d, -200.f), 200.f);        // defensive; algebra exact
                float raw = lg2f(s) + featv * L2E;
                Csum += d;
                A = raw - d;
                eB[nb*NK + j] = ex2f(A);
                if (j == 0) s0B[nb] = A;

                // ---- viterbi: plain float, reference op order -> bit-exact ----
                const ulonglong2* v2p = (const ulonglong2*)(vB + cb*NK);
                float m0=-3.4e38f, m1=-3.4e38f, m2=-3.4e38f, m3=-3.4e38f;
                int   i0=0, i1=1, i2=2, i3=3;
                #pragma unroll
                for (int c = 0; c < NK/4; ++c) {
                    ulonglong2 vv = v2p[c];                // broadcast LDS.128
                    unsigned long long y01 = fadd2(vv.x, tpW[2*c]);   // 2 IEEE RN adds
                    unsigned long long y23 = fadd2(vv.y, tpW[2*c+1]);
                    float y0,y1,y2,y3;
                    upk2(y01, y0, y1); upk2(y23, y2, y3);
                    if (y0 > m0) { m0=y0; i0=4*c+0; }
                    if (y1 > m1) { m1=y1; i1=4*c+1; }
                    if (y2 > m2) { m2=y2; i2=4*c+2; }
                    // p == SEND (last element): masked to -1e4, provably never the
                    // argmax (v-spread << 1e4; at t=0 START wins by ~1e4) -> skip
                    if (c < NK/4 - 1) {
                        if (y3 > m3) { m3=y3; i3=4*c+3; }
                    }
                }
                float bm = m0; int bi = i0;                // first-max tie-break
                if (m1 > bm || (m1 == bm && i1 < bi)) { bm=m1; bi=i1; }
                if (m2 > bm || (m2 == bm && i2 < bi)) { bm=m2; bi=i2; }
                if (m3 > bm || (m3 == bm && i3 < bi)) { bm=m3; bi=i3; }
                vj = bm + featv;                           // emission added AFTER max
                bp[t*NK + j] = (unsigned char)bi;
                vB[nb*NK + j] = vj;

                fq[u] = nf;
            }
            __syncthreads();
        }
    }

    // ---- termination ----
    float rF = 0.f;
    if (act) {
        float te = trans[SEND*NK + j];
        if (j == SEND) te = NEGV;                    // column END masked
        rF = A + te * L2E;                           // forward term (log2 domain)
        red[j] = vj + te;                            // viterbi term (plain, exact)
    }
    // logz via warp reduction over lanes 0..31 won't cover 48 states -> use smem for
    // viterbi terms and do forward terms from a second smem pass kept simple:
    eB[j < NK ? j : NK] = 0.f;                       // scratch clear (harmless)
    if (act) eB[j] = rF;                             // reuse eB slot 0..47
    __syncthreads();

    if (j == 0) {
        // logz = logsumexp(alpha + trans[END])
        float m = -3.4e38f;
        #pragma unroll
        for (int p = 0; p < NK; ++p) m = fmaxf(m, eB[p]);
        float s = 0.f;
        #pragma unroll
        for (int p = 0; p < NK; ++p) s += ex2f(eB[p] - m);
        out[b] = (m + lg2f(s) + Csum) * LN2F;
    }
    if (j == 32) {
        // terminal first-max argmax + smem backtrace (separate warp overlaps logz)
        float bm = -3.4e38f; int last = 0;
        #pragma unroll
        for (int p = 0; p < NK; ++p) {
            float y = red[p];
            if (y > bm) { bm = y; last = p; }
        }
        out[NB + b] = bm;
        float* po = out + 2*NB + (size_t)b * NT;
        int tag = last;
        #pragma unroll 1
        for (int t = NT - 1; t >= 0; --t) {
            po[t] = (float)tag;
            tag = bp[t*NK + tag];
        }
    }
}

extern "C" void kernel_launch(void* const* d_in, const int* in_sizes, int n_in,
                              void* d_out, int out_size)
{
    const float* feats = (const float*)d_in[0];
    const float* trans = (const float*)d_in[1];
    float* out = (float*)d_out;
    cudaFuncSetAttribute(crf_kernel, cudaFuncAttributeMaxDynamicSharedMemorySize,
                         SMEM_BYTES);
    crf_kernel<<<NB, 64, SMEM_BYTES>>>(feats, trans, out);
}

// round 9
// speedup vs baseline: 1.3160x; 1.1064x over previous
#include <cuda_runtime.h>

#define NB 512
#define NT 1024
#define NK 48
#define HK 24
#define SSTART 46
#define SEND 47
#define NEGV (-10000.0f)
#define L2E 1.4426950408889634f
#define LN2F 0.6931471805599453f

// dyn smem: bp[NT*NK] u8 | e[2][NK] | v[2][NK] | s0[2] | red[NK] | fRed[NK]
#define OFF_E    (NT*NK)
#define OFF_V    (OFF_E + 2*NK*4)
#define OFF_S0   (OFF_V + 2*NK*4)
#define OFF_RED  (OFF_S0 + 16)
#define OFF_FRED (OFF_RED + NK*4)
#define SMEM_BYTES (OFF_FRED + NK*4)

#define PD 2   // feats prefetch depth

__device__ __forceinline__ float ex2f(float x){ float y; asm("ex2.approx.ftz.f32 %0, %1;":"=f"(y):"f"(x)); return y; }
__device__ __forceinline__ float lg2f(float x){ float y; asm("lg2.approx.f32 %0, %1;":"=f"(y):"f"(x)); return y; }
__device__ __forceinline__ unsigned long long ffma2(unsigned long long a, unsigned long long b, unsigned long long c){
    unsigned long long d; asm("fma.rn.f32x2 %0, %1, %2, %3;" : "=l"(d) : "l"(a), "l"(b), "l"(c)); return d;
}
__device__ __forceinline__ unsigned long long fadd2(unsigned long long a, unsigned long long b){
    unsigned long long d; asm("add.rn.f32x2 %0, %1, %2;" : "=l"(d) : "l"(a), "l"(b)); return d;
}
__device__ __forceinline__ unsigned long long pk2(float lo, float hi){
    unsigned long long d; asm("mov.b64 %0, {%1, %2};" : "=l"(d) : "f"(lo), "f"(hi)); return d;
}
__device__ __forceinline__ void upk2(unsigned long long v, float& lo, float& hi){
    asm("mov.b64 {%0, %1}, %2;" : "=f"(lo), "=f"(hi) : "l"(v));
}

__global__ __launch_bounds__(192, 4)
void crf_kernel(const float* __restrict__ feats,
                const float* __restrict__ trans,
                float* __restrict__ out)
{
    extern __shared__ char smc[];
    unsigned char* bp  = (unsigned char*)smc;
    float* eB   = (float*)(smc + OFF_E);    // exp2 of normalized log2-alpha, dbl-buffered
    float* vB   = (float*)(smc + OFF_V);    // viterbi values (plain), dbl-buffered
    float* s0B  = (float*)(smc + OFF_S0);   // broadcast normalized A[0] (shift)
    float* red  = (float*)(smc + OFF_RED);  // viterbi terminal terms
    float* fRed = (float*)(smc + OFF_FRED); // forward terminal terms

    const int b   = blockIdx.x;
    const int tid = threadIdx.x;
    const bool isV = (tid < 96);            // warps 0-2: viterbi, warps 3-5: forward
    const int rt   = isV ? tid : (tid - 96);
    const int j    = rt >> 1;               // state (2 threads per state)
    const int half = rt & 1;                // 0: prev 0-23, 1: prev 24-47
    const float* f = feats + (size_t)b * NT * NK;

    // packed half-row of trans for this (state, half): 12 u64
    unsigned long long tp[HK/2];
    float A = 0.f, Csum = 0.f, vj = 0.f;

    #pragma unroll
    for (int c = 0; c < HK/2; ++c) {
        const int p0 = half*HK + 2*c;
        float t0 = trans[j*NK + p0];
        float t1 = trans[j*NK + p0 + 1];
        if (j == SSTART)  { t0 = NEGV; t1 = NEGV; }  // no transition into START row
        if (p0   == SEND)   t0 = NEGV;               // no transition out of END col
        if (p0+1 == SEND)   t1 = NEGV;
        if (isV) tp[c] = pk2(t0, t1);                        // plain (bit-exact path)
        else     tp[c] = pk2(ex2f(t0 * L2E), ex2f(t1 * L2E)); // exp-factored forward
    }
    if (half == 0) {
        if (isV) { vj = (j == SSTART) ? 0.f : NEGV;       vB[j] = vj; }
        else     { A  = (j == SSTART) ? 0.f : NEGV * L2E; eB[j] = (j == SSTART) ? 1.f : 0.f; }
    }
    float fq[PD];
    #pragma unroll
    for (int i = 0; i < PD; ++i) fq[i] = __ldg(f + i*NK + j);
    if (tid == 0) s0B[0] = 0.f;
    __syncthreads();

    #pragma unroll 1
    for (int g = 0; g < NT/PD; ++g) {
        #pragma unroll
        for (int u = 0; u < PD; ++u) {
            const int t  = g*PD + u;
            const int cb = u & 1;            // buffer parity
            const int nb = cb ^ 1;
            const float featv = fq[u];
            float nf = 0.f;
            if (t + PD < NT) nf = __ldg(f + (t+PD)*NK + j);   // prefetch

            if (isV) {
                // viterbi over HALF the prev states (plain float, reference order)
                const ulonglong2* v2p = (const ulonglong2*)(vB + cb*NK + half*HK);
                float m0=-3.4e38f, m1=-3.4e38f, m2=-3.4e38f, m3=-3.4e38f;
                int   i0=0, i1=1, i2=2, i3=3;                 // local indices
                #pragma unroll
                for (int c = 0; c < HK/4; ++c) {
                    ulonglong2 vv = v2p[c];
                    unsigned long long y01 = fadd2(vv.x, tp[2*c]);    // 2 IEEE RN adds
                    unsigned long long y23 = fadd2(vv.y, tp[2*c+1]);
                    float y0,y1,y2,y3;
                    upk2(y01, y0, y1); upk2(y23, y2, y3);
                    if (y0 > m0) { m0=y0; i0=4*c+0; }
                    if (y1 > m1) { m1=y1; i1=4*c+1; }
                    if (y2 > m2) { m2=y2; i2=4*c+2; }
                    if (y3 > m3) { m3=y3; i3=4*c+3; }
                }
                // merge 4 chains, first-max tie-break (local idx), then globalize
                float bm = m0; int bi = i0;
                if (m1 > bm || (m1 == bm && i1 < bi)) { bm=m1; bi=i1; }
                if (m2 > bm || (m2 == bm && i2 < bi)) { bm=m2; bi=i2; }
                if (m3 > bm || (m3 == bm && i3 < bi)) { bm=m3; bi=i3; }
                bi += half*HK;
                // pair-combine: odd half's indices all larger -> strict > keeps
                // first-max semantics exactly
                float om = __shfl_xor_sync(0xffffffffu, bm, 1);
                int   oi = __shfl_xor_sync(0xffffffffu, bi, 1);
                if (half == 0) {
                    if (om > bm) { bm = om; bi = oi; }
                    vj = bm + featv;                 // emission added AFTER max (ref)
                    bp[t*NK + j] = (unsigned char)bi;
                    vB[nb*NK + j] = vj;
                }
            } else {
                // forward: partial matvec over HALF the prev states (packed FFMA)
                const ulonglong2* e2p = (const ulonglong2*)(eB + cb*NK + half*HK);
                unsigned long long acc0 = 0ull, acc1 = 0ull;
                #pragma unroll
                for (int c = 0; c < HK/4; ++c) {
                    ulonglong2 ev = e2p[c];
                    acc0 = ffma2(tp[2*c    ], ev.x, acc0);
                    acc1 = ffma2(tp[2*c + 1], ev.y, acc1);
                }
                float a0l,a0h,a1l,a1h;
                upk2(acc0, a0l, a0h); upk2(acc1, a1l, a1h);
                float sh = (a0l + a0h) + (a1l + a1h);
                float os = __shfl_xor_sync(0xffffffffu, sh, 1);
                float s  = sh + os;                  // commutative -> same on both lanes
                float d = s0B[cb];                   // prev step's normalized A[0]
                d = fminf(fmaxf(d, -200.f), 200.f);  // defensive; algebra stays exact
                float raw = lg2f(s) + featv * L2E;
                Csum += d;
                A = raw - d;
                if (half == 0) {
                    eB[nb*NK + j] = ex2f(A);
                    if (j == 0) s0B[nb] = A;
                }
            }
            fq[u] = nf;
            __syncthreads();
        }
    }

    // ---- termination ----
    if (half == 0) {
        float te = trans[SEND*NK + j];
        if (j == SEND) te = NEGV;                    // column END masked
        if (isV) red[j]  = vj + te;                  // plain, bit-exact
        else     fRed[j] = A  + te * L2E;            // log2 domain (C added at end)
    }
    __syncthreads();

    if (tid == 96) {
        // logz = logsumexp(alpha + trans[END]); this thread holds Csum
        float m = -3.4e38f;
        #pragma unroll
        for (int p = 0; p < NK; ++p) m = fmaxf(m, fRed[p]);
        float s = 0.f;
        #pragma unroll
        for (int p = 0; p < NK; ++p) s += ex2f(fRed[p] - m);
        out[b] = (m + lg2f(s) + Csum) * LN2F;
    }
    if (tid == 0) {
        // terminal first-max argmax + smem backtrace (different warp than logz)
        float bm = -3.4e38f; int last = 0;
        #pragma unroll
        for (int p = 0; p < NK; ++p) {
            float y = red[p];
            if (y > bm) { bm = y; last = p; }
        }
        out[NB + b] = bm;
        float* po = out + 2*NB + (size_t)b * NT;
        int tag = last;
        #pragma unroll 1
        for (int t = NT - 1; t >= 0; --t) {
            po[t] = (float)tag;
            tag = bp[t*NK + tag];
        }
    }
}

extern "C" void kernel_launch(void* const* d_in, const int* in_sizes, int n_in,
                              void* d_out, int out_size)
{
    const float* feats = (const float*)d_in[0];
    const float* trans = (const float*)d_in[1];
    float* out = (float*)d_out;
    cudaFuncSetAttribute(crf_kernel, cudaFuncAttributeMaxDynamicSharedMemorySize,
                         SMEM_BYTES);
    crf_kernel<<<NB, 192, SMEM_BYTES>>>(feats, trans, out);
}

// round 10
// speedup vs baseline: 1.3164x; 1.0003x over previous
#include <cuda_runtime.h>

#define NB 512
#define NT 1024
#define NK 48
#define HK 24
#define SSTART 46
#define SEND 47
#define NEGV (-10000.0f)
#define L2E 1.4426950408889634f
#define LN2F 0.6931471805599453f

// per-batch slot: bp[NT*NK] u8 | e[2][NK] | v[2][NK] | s0[2] | red[NK] | fRed[NK]
#define OFF_E    (NT*NK)
#define OFF_V    (OFF_E + 2*NK*4)
#define OFF_S0   (OFF_V + 2*NK*4)
#define OFF_RED  (OFF_S0 + 16)
#define OFF_FRED (OFF_RED + NK*4)
#define SLOT     (((OFF_FRED + NK*4) + 127) & ~127)
#define SMEM_BYTES (2*SLOT)

#define PD 2   // feats prefetch depth

__device__ __forceinline__ float ex2f(float x){ float y; asm("ex2.approx.ftz.f32 %0, %1;":"=f"(y):"f"(x)); return y; }
__device__ __forceinline__ float lg2f(float x){ float y; asm("lg2.approx.f32 %0, %1;":"=f"(y):"f"(x)); return y; }
__device__ __forceinline__ unsigned long long ffma2(unsigned long long a, unsigned long long b, unsigned long long c){
    unsigned long long d; asm("fma.rn.f32x2 %0, %1, %2, %3;" : "=l"(d) : "l"(a), "l"(b), "l"(c)); return d;
}
__device__ __forceinline__ unsigned long long fadd2(unsigned long long a, unsigned long long b){
    unsigned long long d; asm("add.rn.f32x2 %0, %1, %2;" : "=l"(d) : "l"(a), "l"(b)); return d;
}
__device__ __forceinline__ unsigned long long pk2(float lo, float hi){
    unsigned long long d; asm("mov.b64 %0, {%1, %2};" : "=l"(d) : "f"(lo), "f"(hi)); return d;
}
__device__ __forceinline__ void upk2(unsigned long long v, float& lo, float& hi){
    asm("mov.b64 {%0, %1}, %2;" : "=f"(lo), "=f"(hi) : "l"(v));
}

__global__ __launch_bounds__(192, 2)
void crf_kernel(const float* __restrict__ feats,
                const float* __restrict__ trans,
                float* __restrict__ out)
{
    extern __shared__ char smc[];
    const int tid = threadIdx.x;
    const bool isV = (tid < 96);            // warps 0-2: viterbi, warps 3-5: forward
    const int rt   = isV ? tid : (tid - 96);
    const int j    = rt >> 1;               // state (2 threads per state)
    const int half = rt & 1;                // 0: prev 0-23, 1: prev 24-47

    // per-batch smem pointers (q = 0,1)
    unsigned char* bpQ[2];  float* eBQ[2];  float* vBQ[2];
    float* s0Q[2];          float* redQ[2]; float* frdQ[2];
    const float* fQ[2];
    #pragma unroll
    for (int q = 0; q < 2; ++q) {
        char* sb = smc + q*SLOT;
        bpQ[q]  = (unsigned char*)sb;
        eBQ[q]  = (float*)(sb + OFF_E);
        vBQ[q]  = (float*)(sb + OFF_V);
        s0Q[q]  = (float*)(sb + OFF_S0);
        redQ[q] = (float*)(sb + OFF_RED);
        frdQ[q] = (float*)(sb + OFF_FRED);
        fQ[q]   = feats + (size_t)(blockIdx.x*2 + q) * NT * NK;
    }

    // packed half-row of trans: SHARED across both batches (12 u64)
    unsigned long long tp[HK/2];
    float A[2] = {0.f,0.f}, Csum[2] = {0.f,0.f}, vj[2] = {0.f,0.f};

    #pragma unroll
    for (int c = 0; c < HK/2; ++c) {
        const int p0 = half*HK + 2*c;
        float t0 = trans[j*NK + p0];
        float t1 = trans[j*NK + p0 + 1];
        if (j == SSTART)  { t0 = NEGV; t1 = NEGV; }  // no transition into START row
        if (p0   == SEND)   t0 = NEGV;               // no transition out of END col
        if (p0+1 == SEND)   t1 = NEGV;
        if (isV) tp[c] = pk2(t0, t1);                        // plain (bit-exact path)
        else     tp[c] = pk2(ex2f(t0 * L2E), ex2f(t1 * L2E)); // exp-factored forward
    }
    #pragma unroll
    for (int q = 0; q < 2; ++q) {
        if (half == 0) {
            if (isV) { vj[q] = (j == SSTART) ? 0.f : NEGV;       vBQ[q][j] = vj[q]; }
            else     { A[q]  = (j == SSTART) ? 0.f : NEGV * L2E;
                       eBQ[q][j] = (j == SSTART) ? 1.f : 0.f; }
        }
        if (tid == 0) s0Q[q][0] = 0.f;
    }
    float fq[2][PD];
    #pragma unroll
    for (int q = 0; q < 2; ++q)
        #pragma unroll
        for (int i = 0; i < PD; ++i) fq[q][i] = __ldg(fQ[q] + i*NK + j);
    __syncthreads();

    #pragma unroll 1
    for (int g = 0; g < NT/PD; ++g) {
        #pragma unroll
        for (int u = 0; u < PD; ++u) {
            const int t  = g*PD + u;
            const int cb = u & 1;
            const int nb = cb ^ 1;
            #pragma unroll
            for (int q = 0; q < 2; ++q) {      // two INDEPENDENT batch chains -> ILP
                const float featv = fq[q][u];
                float nf = 0.f;
                if (t + PD < NT) nf = __ldg(fQ[q] + (t+PD)*NK + j);   // prefetch

                if (isV) {
                    // viterbi over half the prev states (plain float, reference order)
                    const ulonglong2* v2p = (const ulonglong2*)(vBQ[q] + cb*NK + half*HK);
                    float m0=-3.4e38f, m1=-3.4e38f, m2=-3.4e38f, m3=-3.4e38f;
                    int   i0=0, i1=1, i2=2, i3=3;
                    #pragma unroll
                    for (int c = 0; c < HK/4; ++c) {
                        ulonglong2 vv = v2p[c];
                        unsigned long long y01 = fadd2(vv.x, tp[2*c]);   // IEEE RN adds
                        unsigned long long y23 = fadd2(vv.y, tp[2*c+1]);
                        float y0,y1,y2,y3;
                        upk2(y01, y0, y1); upk2(y23, y2, y3);
                        if (y0 > m0) { m0=y0; i0=4*c+0; }
                        if (y1 > m1) { m1=y1; i1=4*c+1; }
                        if (y2 > m2) { m2=y2; i2=4*c+2; }
                        if (y3 > m3) { m3=y3; i3=4*c+3; }
                    }
                    float bm = m0; int bi = i0;      // first-max tie-break (local idx)
                    if (m1 > bm || (m1 == bm && i1 < bi)) { bm=m1; bi=i1; }
                    if (m2 > bm || (m2 == bm && i2 < bi)) { bm=m2; bi=i2; }
                    if (m3 > bm || (m3 == bm && i3 < bi)) { bm=m3; bi=i3; }
                    bi += half*HK;
                    // pair-combine: odd half's indices all larger -> strict > exact
                    float om = __shfl_xor_sync(0xffffffffu, bm, 1);
                    int   oi = __shfl_xor_sync(0xffffffffu, bi, 1);
                    if (half == 0) {
                        if (om > bm) { bm = om; bi = oi; }
                        vj[q] = bm + featv;          // emission added AFTER max (ref)
                        bpQ[q][t*NK + j] = (unsigned char)bi;
                        vBQ[q][nb*NK + j] = vj[q];
                    }
                } else {
                    // forward: partial matvec over half the prev states (packed FFMA)
                    const ulonglong2* e2p = (const ulonglong2*)(eBQ[q] + cb*NK + half*HK);
                    unsigned long long acc0 = 0ull, acc1 = 0ull;
                    #pragma unroll
                    for (int c = 0; c < HK/4; ++c) {
                        ulonglong2 ev = e2p[c];
                        acc0 = ffma2(tp[2*c    ], ev.x, acc0);
                        acc1 = ffma2(tp[2*c + 1], ev.y, acc1);
                    }
                    float a0l,a0h,a1l,a1h;
                    upk2(acc0, a0l, a0h); upk2(acc1, a1l, a1h);
                    float sh = (a0l + a0h) + (a1l + a1h);
                    float os = __shfl_xor_sync(0xffffffffu, sh, 1);
                    float s  = sh + os;              // commutative -> same on both lanes
                    float d = s0Q[q][cb];            // prev step's normalized A[0]
                    d = fminf(fmaxf(d, -200.f), 200.f);
                    float raw = lg2f(s) + featv * L2E;
                    Csum[q] += d;
                    A[q] = raw - d;
                    if (half == 0) {
                        eBQ[q][nb*NK + j] = ex2f(A[q]);
                        if (j == 0) s0Q[q][nb] = A[q];
                    }
                }
                fq[q][u] = nf;
            }
            __syncthreads();
        }
    }

    // ---- termination ----
    #pragma unroll
    for (int q = 0; q < 2; ++q) {
        if (half == 0) {
            float te = trans[SEND*NK + j];
            if (j == SEND) te = NEGV;                // column END masked
            if (isV) redQ[q][j] = vj[q] + te;        // plain, bit-exact
            else     frdQ[q][j] = A[q]  + te * L2E;  // log2 domain (C added at end)
        }
    }
    __syncthreads();

    // logz: fwd threads 96 (batch0) and 98 (batch1); Csum is in their registers
    if (!isV && half == 0 && (j == 0 || j == 1)) {
        const int q = j;
        float m = -3.4e38f;
        #pragma unroll
        for (int p = 0; p < NK; ++p) m = fmaxf(m, frdQ[q][p]);
        float s = 0.f;
        #pragma unroll
        for (int p = 0; p < NK; ++p) s += ex2f(frdQ[q][p] - m);
        out[blockIdx.x*2 + q] = (m + lg2f(s) + Csum[q]) * LN2F;
    }
    // backtrace: threads 0 (batch0) and 32 (batch1) -> different warps, concurrent
    if (isV && (tid == 0 || tid == 32)) {
        const int q = (tid == 0) ? 0 : 1;
        float bm = -3.4e38f; int last = 0;
        #pragma unroll
        for (int p = 0; p < NK; ++p) {
            float y = redQ[q][p];
            if (y > bm) { bm = y; last = p; }
        }
        const int b = blockIdx.x*2 + q;
        out[NB + b] = bm;
        float* po = out + 2*NB + (size_t)b * NT;
        int tag = last;
        #pragma unroll 1
        for (int t = NT - 1; t >= 0; --t) {
            po[t] = (float)tag;
            tag = bpQ[q][t*NK + tag];
        }
    }
}

extern "C" void kernel_launch(void* const* d_in, const int* in_sizes, int n_in,
                              void* d_out, int out_size)
{
    const float* feats = (const float*)d_in[0];
    const float* trans = (const float*)d_in[1];
    float* out = (float*)d_out;
    cudaFuncSetAttribute(crf_kernel, cudaFuncAttributeMaxDynamicSharedMemorySize,
                         SMEM_BYTES);
    cudaFuncSetAttribute(crf_kernel, cudaFuncAttributePreferredSharedMemoryCarveout,
                         100);
    crf_kernel<<<NB/2, 192, SMEM_BYTES>>>(feats, trans, out);
}

// round 11
// speedup vs baseline: 1.6961x; 1.2885x over previous
#include <cuda_runtime.h>

#define NB 512
#define NT 1024
#define NK 48
#define SSTART 46
#define SEND 47
#define NEGV (-10000.0f)
#define L2E 1.4426950408889634f
#define LN2F 0.6931471805599453f

// per-batch slot: bp[NT*NK] u8 | v[NK] f32 (+pad) | e[NK] f32 (+pad)
#define SLOT_V  (NT*NK)
#define SLOT_E  (SLOT_V + 256)
#define SLOT    (SLOT_E + 256)
#define SMEM_BYTES (4*SLOT)     // 198656 <= 227KB -> 1 CTA/SM

__device__ __forceinline__ float ex2f(float x){ float y; asm("ex2.approx.ftz.f32 %0, %1;":"=f"(y):"f"(x)); return y; }
__device__ __forceinline__ float lg2f(float x){ float y; asm("lg2.approx.f32 %0, %1;":"=f"(y):"f"(x)); return y; }
__device__ __forceinline__ unsigned long long ffma2(unsigned long long a, unsigned long long b, unsigned long long c){
    unsigned long long d; asm("fma.rn.f32x2 %0, %1, %2, %3;" : "=l"(d) : "l"(a), "l"(b), "l"(c)); return d;
}
__device__ __forceinline__ unsigned long long fadd2(unsigned long long a, unsigned long long b){
    unsigned long long d; asm("add.rn.f32x2 %0, %1, %2;" : "=l"(d) : "l"(a), "l"(b)); return d;
}
__device__ __forceinline__ unsigned long long pk2(float lo, float hi){
    unsigned long long d; asm("mov.b64 %0, {%1, %2};" : "=l"(d) : "f"(lo), "f"(hi)); return d;
}
__device__ __forceinline__ void upk2(unsigned long long v, float& lo, float& hi){
    asm("mov.b64 {%0, %1}, %2;" : "=f"(lo), "=f"(hi) : "l"(v));
}

// full-row viterbi scan for one state: 4 interleaved chains + exact first-max merge
#define VIT_STATE(tp, bm, bi) do { \
    float m0=-3.4e38f,m1=-3.4e38f,m2=-3.4e38f,m3=-3.4e38f; \
    int i0=0,i1=1,i2=2,i3=3; \
    _Pragma("unroll") \
    for (int c=0;c<12;++c){ \
        unsigned long long y01=fadd2(vv[c].x,(tp)[2*c]); \
        unsigned long long y23=fadd2(vv[c].y,(tp)[2*c+1]); \
        float y0,y1,y2,y3; upk2(y01,y0,y1); upk2(y23,y2,y3); \
        if(y0>m0){m0=y0;i0=4*c+0;} \
        if(y1>m1){m1=y1;i1=4*c+1;} \
        if(y2>m2){m2=y2;i2=4*c+2;} \
        if(y3>m3){m3=y3;i3=4*c+3;} } \
    bm=m0; bi=i0; \
    if(m1>bm||(m1==bm&&i1<bi)){bm=m1;bi=i1;} \
    if(m2>bm||(m2==bm&&i2<bi)){bm=m2;bi=i2;} \
    if(m3>bm||(m3==bm&&i3<bi)){bm=m3;bi=i3;} \
} while(0)

__global__ __launch_bounds__(256, 1)
void crf_kernel(const float* __restrict__ feats,
                const float* __restrict__ trans,
                float* __restrict__ out)
{
    extern __shared__ char smc[];
    const int tid  = threadIdx.x;
    const int wid  = tid >> 5;
    const int lane = tid & 31;
    const int q    = wid & 3;                        // batch within CTA
    // role interleave: SMSP w%4 gets exactly one vit + one fwd warp
    const bool isV = ((wid & 1) == (wid >> 2));
    const int b = blockIdx.x * 4 + q;
    char* sb = smc + q * SLOT;
    unsigned char* bp = (unsigned char*)sb;
    float* vS = (float*)(sb + SLOT_V);               // viterbi state vector
    float* eS = (float*)(sb + SLOT_E);               // exp2(normalized log2-alpha)
    const float* f = feats + (size_t)b * NT * NK;

    const int  ll  = (lane < 24) ? lane : (lane - 24);
    const bool act = (lane < 24);                    // lanes 24-31: harmless duplicates
    const int  j1  = ll, j2 = ll + 24;               // two states per lane

    // two trans rows per lane (48 floats packed as 24 u64 each)
    unsigned long long tpA[NK/2], tpB[NK/2];
    #pragma unroll
    for (int c = 0; c < NK/2; ++c) {
        const int p0 = 2*c, p1 = 2*c + 1;
        float a0 = trans[j1*NK+p0], a1 = trans[j1*NK+p1];
        float c0 = trans[j2*NK+p0], c1 = trans[j2*NK+p1];
        if (j1 == SSTART) { a0 = NEGV; a1 = NEGV; }  // no transition into START row
        if (j2 == SSTART) { c0 = NEGV; c1 = NEGV; }
        if (p0 == SEND)   { a0 = NEGV; c0 = NEGV; }  // no transition out of END col
        if (p1 == SEND)   { a1 = NEGV; c1 = NEGV; }
        if (isV) { tpA[c] = pk2(a0, a1); tpB[c] = pk2(c0, c1); }   // plain (bit-exact)
        else     { tpA[c] = pk2(ex2f(a0*L2E), ex2f(a1*L2E));        // exp-factored
                   tpB[c] = pk2(ex2f(c0*L2E), ex2f(c1*L2E)); }      // masked -> exact 0
    }
    if (act) {
        if (isV) { vS[j1] = (j1==SSTART)?0.f:NEGV;  vS[j2] = (j2==SSTART)?0.f:NEGV; }
        else     { eS[j1] = (j1==SSTART)?1.f:0.f;   eS[j2] = (j2==SSTART)?1.f:0.f; }
    }
    __syncwarp();

    float fq1[2], fq2[2];                            // 2-step feats prefetch
    fq1[0] = __ldg(f + j1);      fq2[0] = __ldg(f + j2);
    fq1[1] = __ldg(f + NK + j1); fq2[1] = __ldg(f + NK + j2);

    if (isV) {
        // ================= VITERBI: self-contained warp, no CTA barriers =======
        #pragma unroll 1
        for (int g = 0; g < NT/2; ++g) {
            #pragma unroll
            for (int u = 0; u < 2; ++u) {
                const int t = g*2 + u;
                ulonglong2 vv[12];
                const ulonglong2* vp = (const ulonglong2*)vS;
                #pragma unroll
                for (int c = 0; c < 12; ++c) vv[c] = vp[c];        // broadcast LDS.128
                const float featv1 = fq1[u], featv2 = fq2[u];
                if (t + 2 < NT) { fq1[u] = __ldg(f + (t+2)*NK + j1);
                                  fq2[u] = __ldg(f + (t+2)*NK + j2); }
                float bm1, bm2; int bi1, bi2;
                VIT_STATE(tpA, bm1, bi1);            // plain float, reference op order
                VIT_STATE(tpB, bm2, bi2);
                __syncwarp();                         // all lanes done reading old v
                if (act) {
                    vS[j1] = bm1 + featv1;            // emission added AFTER max (ref)
                    vS[j2] = bm2 + featv2;
                    bp[t*NK + j1] = (unsigned char)bi1;
                    bp[t*NK + j2] = (unsigned char)bi2;
                }
                __syncwarp();                         // new v visible warp-wide
            }
        }
        if (lane == 0) {
            // terminal first-max argmax + backtrace (warp-private, serial tail)
            float bm = -3.4e38f; int last = 0;
            #pragma unroll
            for (int p = 0; p < NK; ++p) {
                float te = trans[SEND*NK + p];
                if (p == SEND) te = NEGV;
                float y = vS[p] + te;
                if (y > bm) { bm = y; last = p; }
            }
            out[NB + b] = bm;
            float* po = out + 2*NB + (size_t)b * NT;
            int tag = last;
            #pragma unroll 1
            for (int t = NT - 1; t >= 0; --t) {
                po[t] = (float)tag;
                tag = bp[t*NK + tag];
            }
        }
    } else {
        // ================= FORWARD: self-contained warp ========================
        float Csum = 0.f, A1 = 0.f, A2 = 0.f;
        #pragma unroll 1
        for (int g = 0; g < NT/2; ++g) {
            #pragma unroll
            for (int u = 0; u < 2; ++u) {
                const int t = g*2 + u;
                ulonglong2 vv[12];
                const ulonglong2* ep = (const ulonglong2*)eS;
                #pragma unroll
                for (int c = 0; c < 12; ++c) vv[c] = ep[c];        // broadcast LDS.128
                const float featv1 = fq1[u], featv2 = fq2[u];
                if (t + 2 < NT) { fq1[u] = __ldg(f + (t+2)*NK + j1);
                                  fq2[u] = __ldg(f + (t+2)*NK + j2); }
                unsigned long long a0=0ull, a1=0ull, a2=0ull, a3=0ull;
                #pragma unroll
                for (int c = 0; c < 12; ++c) {                     // packed f32x2 FFMA
                    a0 = ffma2(tpA[2*c  ], vv[c].x, a0);
                    a1 = ffma2(tpA[2*c+1], vv[c].y, a1);
                    a2 = ffma2(tpB[2*c  ], vv[c].x, a2);
                    a3 = ffma2(tpB[2*c+1], vv[c].y, a3);
                }
                float x0,x1,x2,x3,x4,x5,x6,x7;
                upk2(a0,x0,x1); upk2(a1,x2,x3); upk2(a2,x4,x5); upk2(a3,x6,x7);
                float s1 = (x0+x1)+(x2+x3);
                float s2 = (x4+x5)+(x6+x7);
                float raw1 = lg2f(s1) + featv1 * L2E;
                float raw2 = lg2f(s2) + featv2 * L2E;
                // shift by CURRENT raw[0] (lane 0 owns state 0): exact, well-damped
                float d = __shfl_sync(0xffffffffu, raw1, 0);
                d = fminf(fmaxf(d, -200.f), 200.f);   // defensive; algebra stays exact
                Csum += d;
                A1 = raw1 - d; A2 = raw2 - d;
                __syncwarp();                         // all lanes done reading old e
                if (act) { eS[j1] = ex2f(A1); eS[j2] = ex2f(A2); }
                __syncwarp();                         // new e visible warp-wide
            }
        }
        // terminal: reuse eS as scratch for normalized log2-alpha
        __syncwarp();
        if (act) { eS[j1] = A1; eS[j2] = A2; }
        __syncwarp();
        if (lane == 0) {
            float m = -3.4e38f;
            #pragma unroll
            for (int p = 0; p < NK; ++p) {
                float te = trans[SEND*NK + p];
                if (p == SEND) te = NEGV;
                m = fmaxf(m, eS[p] + te * L2E);
            }
            float s = 0.f;
            #pragma unroll
            for (int p = 0; p < NK; ++p) {
                float te = trans[SEND*NK + p];
                if (p == SEND) te = NEGV;
                s += ex2f(eS[p] + te * L2E - m);
            }
            out[b] = (m + lg2f(s) + Csum) * LN2F;
        }
    }
}

extern "C" void kernel_launch(void* const* d_in, const int* in_sizes, int n_in,
                              void* d_out, int out_size)
{
    const float* feats = (const float*)d_in[0];
    const float* trans = (const float*)d_in[1];
    float* out = (float*)d_out;
    cudaFuncSetAttribute(crf_kernel, cudaFuncAttributeMaxDynamicSharedMemorySize,
                         SMEM_BYTES);
    cudaFuncSetAttribute(crf_kernel, cudaFuncAttributePreferredSharedMemoryCarveout,
                         100);
    crf_kernel<<<NB/4, 256, SMEM_BYTES>>>(feats, trans, out);
}

// round 12
// speedup vs baseline: 1.7570x; 1.0359x over previous
#include <cuda_runtime.h>

#define NB 512
#define NT 1024
#define NK 48
#define SSTART 46
#define SEND 47
#define NEGV (-10000.0f)
#define L2E 1.4426950408889634f
#define LN2F 0.6931471805599453f

// per-batch slot: bp[NT*NK] u8 | v0[NK] | v1[NK] | e0[NK] | e1[NK] (each padded)
#define SLOT_V0 (NT*NK)
#define SLOT_V1 (SLOT_V0 + 256)
#define SLOT_E0 (SLOT_V1 + 256)
#define SLOT_E1 (SLOT_E0 + 256)
#define SLOT    (SLOT_E1 + 256)
#define SMEM_BYTES (4*SLOT)     // ~199.7KB -> 1 CTA/SM

__device__ __forceinline__ float ex2f(float x){ float y; asm("ex2.approx.ftz.f32 %0, %1;":"=f"(y):"f"(x)); return y; }
__device__ __forceinline__ float lg2f(float x){ float y; asm("lg2.approx.f32 %0, %1;":"=f"(y):"f"(x)); return y; }
__device__ __forceinline__ unsigned long long ffma2(unsigned long long a, unsigned long long b, unsigned long long c){
    unsigned long long d; asm("fma.rn.f32x2 %0, %1, %2, %3;" : "=l"(d) : "l"(a), "l"(b), "l"(c)); return d;
}
__device__ __forceinline__ unsigned long long fadd2(unsigned long long a, unsigned long long b){
    unsigned long long d; asm("add.rn.f32x2 %0, %1, %2;" : "=l"(d) : "l"(a), "l"(b)); return d;
}
__device__ __forceinline__ unsigned long long pk2(float lo, float hi){
    unsigned long long d; asm("mov.b64 %0, {%1, %2};" : "=l"(d) : "f"(lo), "f"(hi)); return d;
}
__device__ __forceinline__ void upk2(unsigned long long v, float& lo, float& hi){
    asm("mov.b64 {%0, %1}, %2;" : "=f"(lo), "=f"(hi) : "l"(v));
}

// full-row viterbi scan: 4 interleaved chains + exact first-max merge.
// chain-3 skips c==11 (p=47=SEND, masked to -1e4: provably never the argmax)
#define VIT_STATE(tp, bm, bi) do { \
    float m0=-3.4e38f,m1=-3.4e38f,m2=-3.4e38f,m3=-3.4e38f; \
    int i0=0,i1=1,i2=2,i3=3; \
    _Pragma("unroll") \
    for (int c=0;c<12;++c){ \
        unsigned long long y01=fadd2(vv[c].x,(tp)[2*c]); \
        unsigned long long y23=fadd2(vv[c].y,(tp)[2*c+1]); \
        float y0,y1,y2,y3; upk2(y01,y0,y1); upk2(y23,y2,y3); \
        if(y0>m0){m0=y0;i0=4*c+0;} \
        if(y1>m1){m1=y1;i1=4*c+1;} \
        if(y2>m2){m2=y2;i2=4*c+2;} \
        if(c!=11){ if(y3>m3){m3=y3;i3=4*c+3;} } \
    } \
    bm=m0; bi=i0; \
    if(m1>bm||(m1==bm&&i1<bi)){bm=m1;bi=i1;} \
    if(m2>bm||(m2==bm&&i2<bi)){bm=m2;bi=i2;} \
    if(m3>bm||(m3==bm&&i3<bi)){bm=m3;bi=i3;} \
} while(0)

__global__ __launch_bounds__(256, 1)
void crf_kernel(const float* __restrict__ feats,
                const float* __restrict__ trans,
                float* __restrict__ out)
{
    extern __shared__ char smc[];
    const int tid  = threadIdx.x;
    const int wid  = tid >> 5;
    const int lane = tid & 31;
    const int q    = wid & 3;                        // batch within CTA
    const bool isV = ((wid & 1) == (wid >> 2));      // SMSP gets 1 vit + 1 fwd
    const int b = blockIdx.x * 4 + q;
    char* sb = smc + q * SLOT;
    unsigned char* bp = (unsigned char*)sb;
    float* vS[2] = { (float*)(sb + SLOT_V0), (float*)(sb + SLOT_V1) };
    float* eS[2] = { (float*)(sb + SLOT_E0), (float*)(sb + SLOT_E1) };
    const float* f = feats + (size_t)b * NT * NK;

    const int  ll  = (lane < 24) ? lane : (lane - 24);
    const bool act = (lane < 24);
    const int  j1  = ll, j2 = ll + 24;               // two states per lane

    unsigned long long tpA[NK/2], tpB[NK/2];
    #pragma unroll
    for (int c = 0; c < NK/2; ++c) {
        const int p0 = 2*c, p1 = 2*c + 1;
        float a0 = trans[j1*NK+p0], a1 = trans[j1*NK+p1];
        float c0 = trans[j2*NK+p0], c1 = trans[j2*NK+p1];
        if (j1 == SSTART) { a0 = NEGV; a1 = NEGV; }  // no transition into START row
        if (j2 == SSTART) { c0 = NEGV; c1 = NEGV; }
        if (p0 == SEND)   { a0 = NEGV; c0 = NEGV; }  // no transition out of END col
        if (p1 == SEND)   { a1 = NEGV; c1 = NEGV; }
        if (isV) { tpA[c] = pk2(a0, a1); tpB[c] = pk2(c0, c1); }     // plain (exact)
        else     { tpA[c] = pk2(ex2f(a0*L2E), ex2f(a1*L2E));          // exp-factored
                   tpB[c] = pk2(ex2f(c0*L2E), ex2f(c1*L2E)); }        // masked -> 0
    }
    if (act) {
        if (isV) { vS[0][j1] = (j1==SSTART)?0.f:NEGV;  vS[0][j2] = (j2==SSTART)?0.f:NEGV; }
        else     { eS[0][j1] = (j1==SSTART)?1.f:0.f;   eS[0][j2] = (j2==SSTART)?1.f:0.f; }
    }
    __syncwarp();

    float fq1[2], fq2[2];                            // 2-step feats prefetch
    fq1[0] = __ldg(f + j1);      fq2[0] = __ldg(f + j2);
    fq1[1] = __ldg(f + NK + j1); fq2[1] = __ldg(f + NK + j2);

    if (isV) {
        // ====== VITERBI: warp-private, double-buffered, ONE syncwarp/step ======
        #pragma unroll 1
        for (int g = 0; g < NT/2; ++g) {
            #pragma unroll
            for (int u = 0; u < 2; ++u) {            // u: read buf u, write buf u^1
                const int t = g*2 + u;
                ulonglong2 vv[12];
                const ulonglong2* vp = (const ulonglong2*)vS[u];
                #pragma unroll
                for (int c = 0; c < 12; ++c) vv[c] = vp[c];        // broadcast LDS.128
                const float featv1 = fq1[u], featv2 = fq2[u];
                if (t + 2 < NT) { fq1[u] = __ldg(f + (t+2)*NK + j1);
                                  fq2[u] = __ldg(f + (t+2)*NK + j2); }
                float bm1, bm2; int bi1, bi2;
                VIT_STATE(tpA, bm1, bi1);            // plain float, reference op order
                VIT_STATE(tpB, bm2, bi2);
                if (act) {
                    vS[u^1][j1] = bm1 + featv1;      // emission added AFTER max (ref)
                    vS[u^1][j2] = bm2 + featv2;
                    // paired bp layout: byte 2*ll <- j1, byte 2*ll+1 <- j2 (one STS.U16)
                    *(unsigned short*)(bp + t*NK + 2*ll) =
                        (unsigned short)(bi1 | (bi2 << 8));
                }
                __syncwarp();                         // new buffer visible warp-wide
            }
        }
        if (lane == 0) {
            // terminal first-max argmax + backtrace (final state in buf 0)
            float bm = -3.4e38f; int last = 0;
            #pragma unroll
            for (int p = 0; p < NK; ++p) {
                float te = trans[SEND*NK + p];
                if (p == SEND) te = NEGV;
                float y = vS[0][p] + te;
                if (y > bm) { bm = y; last = p; }
            }
            out[NB + b] = bm;
            float* po = out + 2*NB + (size_t)b * NT;
            int tag = last;
            #pragma unroll 1
            for (int t = NT - 1; t >= 0; --t) {
                po[t] = (float)tag;
                // paired layout: state s at byte (s<24 ? 2s : 2s-47)
                int off = (tag < 24) ? (2*tag) : (2*tag - 47);
                tag = bp[t*NK + off];
            }
        }
    } else {
        // ====== FORWARD: warp-private, double-buffered, ONE syncwarp/step ======
        float Csum = 0.f, A1 = 0.f, A2 = 0.f;
        #pragma unroll 1
        for (int g = 0; g < NT/2; ++g) {
            #pragma unroll
            for (int u = 0; u < 2; ++u) {
                const int t = g*2 + u;
                ulonglong2 vv[12];
                const ulonglong2* ep = (const ulonglong2*)eS[u];
                #pragma unroll
                for (int c = 0; c < 12; ++c) vv[c] = ep[c];        // broadcast LDS.128
                const float featv1 = fq1[u], featv2 = fq2[u];
                if (t + 2 < NT) { fq1[u] = __ldg(f + (t+2)*NK + j1);
                                  fq2[u] = __ldg(f + (t+2)*NK + j2); }
                unsigned long long a0=0ull, a1=0ull, a2=0ull, a3=0ull;
                #pragma unroll
                for (int c = 0; c < 12; ++c) {                     // packed f32x2 FFMA
                    a0 = ffma2(tpA[2*c  ], vv[c].x, a0);
                    a1 = ffma2(tpA[2*c+1], vv[c].y, a1);
                    a2 = ffma2(tpB[2*c  ], vv[c].x, a2);
                    a3 = ffma2(tpB[2*c+1], vv[c].y, a3);
                }
                float x0,x1,x2,x3,x4,x5,x6,x7;
                upk2(a0,x0,x1); upk2(a1,x2,x3); upk2(a2,x4,x5); upk2(a3,x6,x7);
                float s1 = (x0+x1)+(x2+x3);
                float s2 = (x4+x5)+(x6+x7);
                float raw1 = lg2f(s1) + featv1 * L2E;
                float raw2 = lg2f(s2) + featv2 * L2E;
                // shift by CURRENT raw[0] (lane 0 owns state 0): exact, well-damped
                float d = __shfl_sync(0xffffffffu, raw1, 0);
                d = fminf(fmaxf(d, -200.f), 200.f);
                Csum += d;
                A1 = raw1 - d; A2 = raw2 - d;
                if (act) { eS[u^1][j1] = ex2f(A1); eS[u^1][j2] = ex2f(A2); }
                __syncwarp();
            }
        }
        // terminal: write normalized log2-alpha to buf 1 as scratch
        if (act) { eS[1][j1] = A1; eS[1][j2] = A2; }
        __syncwarp();
        if (lane == 0) {
            float m = -3.4e38f;
            #pragma unroll
            for (int p = 0; p < NK; ++p) {
                float te = trans[SEND*NK + p];
                if (p == SEND) te = NEGV;
                m = fmaxf(m, eS[1][p] + te * L2E);
            }
            float s = 0.f;
            #pragma unroll
            for (int p = 0; p < NK; ++p) {
                float te = trans[SEND*NK + p];
                if (p == SEND) te = NEGV;
                s += ex2f(eS[1][p] + te * L2E - m);
            }
            out[b] = (m + lg2f(s) + Csum) * LN2F;
        }
    }
}

extern "C" void kernel_launch(void* const* d_in, const int* in_sizes, int n_in,
                              void* d_out, int out_size)
{
    const float* feats = (const float*)d_in[0];
    const float* trans = (const float*)d_in[1];
    float* out = (float*)d_out;
    cudaFuncSetAttribute(crf_kernel, cudaFuncAttributeMaxDynamicSharedMemorySize,
                         SMEM_BYTES);
    cudaFuncSetAttribute(crf_kernel, cudaFuncAttributePreferredSharedMemoryCarveout,
                         100);
    crf_kernel<<<NB/4, 256, SMEM_BYTES>>>(feats, trans, out);
}

// round 13
// speedup vs baseline: 2.0597x; 1.1723x over previous
#include <cuda_runtime.h>

#define NB 512
#define NT 1024
#define NK 48
#define SSTART 46
#define SEND 47
#define NEGV (-10000.0f)
#define L2E 1.4426950408889634f
#define LN2F 0.6931471805599453f

// per-batch slot: bp[NT*NK] u8 | v0[NK] | v1[NK] | e0[NK] | e1[NK] (each padded)
#define SLOT_V0 (NT*NK)
#define SLOT_V1 (SLOT_V0 + 256)
#define SLOT_E0 (SLOT_V1 + 256)
#define SLOT_E1 (SLOT_E0 + 256)
#define SLOT    (SLOT_E1 + 256)
#define TT_OFF  (4*SLOT)                     // masked trans table (shared by batches)
#define SMEM_BYTES (TT_OFF + NK*NK*4)        // ~209.9KB -> 1 CTA/SM

__device__ __forceinline__ float ex2f(float x){ float y; asm("ex2.approx.ftz.f32 %0, %1;":"=f"(y):"f"(x)); return y; }
__device__ __forceinline__ float lg2f(float x){ float y; asm("lg2.approx.f32 %0, %1;":"=f"(y):"f"(x)); return y; }
__device__ __forceinline__ unsigned long long ffma2(unsigned long long a, unsigned long long b, unsigned long long c){
    unsigned long long d; asm("fma.rn.f32x2 %0, %1, %2, %3;" : "=l"(d) : "l"(a), "l"(b), "l"(c)); return d;
}
__device__ __forceinline__ unsigned long long fadd2(unsigned long long a, unsigned long long b){
    unsigned long long d; asm("add.rn.f32x2 %0, %1, %2;" : "=l"(d) : "l"(a), "l"(b)); return d;
}
__device__ __forceinline__ unsigned long long pk2(float lo, float hi){
    unsigned long long d; asm("mov.b64 %0, {%1, %2};" : "=l"(d) : "f"(lo), "f"(hi)); return d;
}
__device__ __forceinline__ void upk2(unsigned long long v, float& lo, float& hi){
    asm("mov.b64 {%0, %1}, %2;" : "=f"(lo), "=f"(hi) : "l"(v));
}

// coarse argmax: exact max via FMNMX groups of 4 (1.5 inst/elem), index recovered
// off the critical path by recomputing the winning group's 4 candidates from smem
// (bit-identical FADDs) and taking the FIRST equal to bm -> first-max semantics.
#define VIT_STATE2(tp, jj, bm, bi) do { \
    bm = -3.4e38f; int g4 = 0; \
    _Pragma("unroll") \
    for (int c=0;c<12;++c){ \
        unsigned long long y01=fadd2(vv[c].x,(tp)[2*c]); \
        unsigned long long y23=fadd2(vv[c].y,(tp)[2*c+1]); \
        float y0,y1,y2,y3; upk2(y01,y0,y1); upk2(y23,y2,y3); \
        float mg = fmaxf(fmaxf(y0,y1), fmaxf(y2,y3)); \
        if (mg > bm) { bm = mg; g4 = c; }   /* strict > keeps earliest group */ \
    } \
    const int p0 = 4*g4; \
    const float* trow = tT + (jj)*NK + p0; \
    float r0 = vcur[p0  ] + trow[0]; \
    float r1 = vcur[p0+1] + trow[1]; \
    float r2 = vcur[p0+2] + trow[2]; \
    bi = (r0==bm) ? p0 : (r1==bm) ? (p0+1) : (r2==bm) ? (p0+2) : (p0+3); \
} while(0)

__global__ __launch_bounds__(256, 1)
void crf_kernel(const float* __restrict__ feats,
                const float* __restrict__ trans,
                float* __restrict__ out)
{
    extern __shared__ char smc[];
    const int tid  = threadIdx.x;
    const int wid  = tid >> 5;
    const int lane = tid & 31;
    const int q    = wid & 3;                        // batch within CTA
    const bool isV = ((wid & 1) == (wid >> 2));      // SMSP gets 1 vit + 1 fwd
    const int b = blockIdx.x * 4 + q;
    char* sb = smc + q * SLOT;
    unsigned char* bp = (unsigned char*)sb;
    float* vS[2] = { (float*)(sb + SLOT_V0), (float*)(sb + SLOT_V1) };
    float* eS[2] = { (float*)(sb + SLOT_E0), (float*)(sb + SLOT_E1) };
    float* tT = (float*)(smc + TT_OFF);              // masked trans table (plain)
    const float* f = feats + (size_t)b * NT * NK;

    // cooperative fill of the masked trans table (one-time)
    for (int idx = tid; idx < NK*NK; idx += 256) {
        const int r = idx / NK, cpos = idx % NK;
        float tv = trans[idx];
        if (r == SSTART) tv = NEGV;                  // no transition into START row
        if (cpos == SEND) tv = NEGV;                 // no transition out of END col
        tT[idx] = tv;
    }

    const int  ll  = (lane < 24) ? lane : (lane - 24);
    const bool act = (lane < 24);
    const int  j1  = ll, j2 = ll + 24;               // two states per lane

    unsigned long long tpA[NK/2], tpB[NK/2];
    #pragma unroll
    for (int c = 0; c < NK/2; ++c) {
        const int p0 = 2*c, p1 = 2*c + 1;
        float a0 = trans[j1*NK+p0], a1 = trans[j1*NK+p1];
        float c0 = trans[j2*NK+p0], c1 = trans[j2*NK+p1];
        if (j1 == SSTART) { a0 = NEGV; a1 = NEGV; }
        if (j2 == SSTART) { c0 = NEGV; c1 = NEGV; }
        if (p0 == SEND)   { a0 = NEGV; c0 = NEGV; }
        if (p1 == SEND)   { a1 = NEGV; c1 = NEGV; }
        if (isV) { tpA[c] = pk2(a0, a1); tpB[c] = pk2(c0, c1); }     // plain (exact)
        else     { tpA[c] = pk2(ex2f(a0*L2E), ex2f(a1*L2E));          // exp-factored
                   tpB[c] = pk2(ex2f(c0*L2E), ex2f(c1*L2E)); }        // masked -> 0
    }
    if (act) {
        if (isV) { vS[0][j1] = (j1==SSTART)?0.f:NEGV;  vS[0][j2] = (j2==SSTART)?0.f:NEGV; }
        else     { eS[0][j1] = (j1==SSTART)?1.f:0.f;   eS[0][j2] = (j2==SSTART)?1.f:0.f; }
    }
    __syncthreads();                                  // table + init visible; then free-run

    float fq1[2], fq2[2];                            // 2-step feats prefetch
    fq1[0] = __ldg(f + j1);      fq2[0] = __ldg(f + j2);
    fq1[1] = __ldg(f + NK + j1); fq2[1] = __ldg(f + NK + j2);

    if (isV) {
        // ====== VITERBI: warp-private, double-buffered, ONE syncwarp/step ======
        #pragma unroll 1
        for (int g = 0; g < NT/2; ++g) {
            #pragma unroll
            for (int u = 0; u < 2; ++u) {            // read buf u, write buf u^1
                const int t = g*2 + u;
                const float* vcur = vS[u];
                ulonglong2 vv[12];
                const ulonglong2* vp = (const ulonglong2*)vcur;
                #pragma unroll
                for (int c = 0; c < 12; ++c) vv[c] = vp[c];        // broadcast LDS.128
                const float featv1 = fq1[u], featv2 = fq2[u];
                if (t + 2 < NT) { fq1[u] = __ldg(f + (t+2)*NK + j1);
                                  fq2[u] = __ldg(f + (t+2)*NK + j2); }
                float bm1, bm2; int bi1, bi2;
                VIT_STATE2(tpA, j1, bm1, bi1);       // plain float, exact max
                VIT_STATE2(tpB, j2, bm2, bi2);
                if (act) {
                    vS[u^1][j1] = bm1 + featv1;      // emission added AFTER max (ref)
                    vS[u^1][j2] = bm2 + featv2;
                    *(unsigned short*)(bp + t*NK + 2*ll) =
                        (unsigned short)(bi1 | (bi2 << 8));
                }
                __syncwarp();
            }
        }
        if (lane == 0) {
            float bm = -3.4e38f; int last = 0;
            #pragma unroll
            for (int p = 0; p < NK; ++p) {
                float te = trans[SEND*NK + p];
                if (p == SEND) te = NEGV;
                float y = vS[0][p] + te;
                if (y > bm) { bm = y; last = p; }
            }
            out[NB + b] = bm;
            float* po = out + 2*NB + (size_t)b * NT;
            int tag = last;
            #pragma unroll 1
            for (int t = NT - 1; t >= 0; --t) {
                po[t] = (float)tag;
                int off = (tag < 24) ? (2*tag) : (2*tag - 47);
                tag = bp[t*NK + off];
            }
        }
    } else {
        // ====== FORWARD: warp-private, double-buffered, ONE syncwarp/step ======
        float Csum = 0.f, A1 = 0.f, A2 = 0.f;
        #pragma unroll 1
        for (int g = 0; g < NT/2; ++g) {
            #pragma unroll
            for (int u = 0; u < 2; ++u) {
                const int t = g*2 + u;
                ulonglong2 vv[12];
                const ulonglong2* ep = (const ulonglong2*)eS[u];
                #pragma unroll
                for (int c = 0; c < 12; ++c) vv[c] = ep[c];        // broadcast LDS.128
                const float featv1 = fq1[u], featv2 = fq2[u];
                if (t + 2 < NT) { fq1[u] = __ldg(f + (t+2)*NK + j1);
                                  fq2[u] = __ldg(f + (t+2)*NK + j2); }
                unsigned long long a0=0ull, a1=0ull, a2=0ull, a3=0ull;
                #pragma unroll
                for (int c = 0; c < 12; ++c) {                     // packed f32x2 FFMA
                    a0 = ffma2(tpA[2*c  ], vv[c].x, a0);
                    a1 = ffma2(tpA[2*c+1], vv[c].y, a1);
                    a2 = ffma2(tpB[2*c  ], vv[c].x, a2);
                    a3 = ffma2(tpB[2*c+1], vv[c].y, a3);
                }
                float x0,x1,x2,x3,x4,x5,x6,x7;
                upk2(a0,x0,x1); upk2(a1,x2,x3); upk2(a2,x4,x5); upk2(a3,x6,x7);
                float s1 = (x0+x1)+(x2+x3);
                float s2 = (x4+x5)+(x6+x7);
                float raw1 = lg2f(s1) + featv1 * L2E;
                float raw2 = lg2f(s2) + featv2 * L2E;
                float d = __shfl_sync(0xffffffffu, raw1, 0);   // current raw[0] shift
                d = fminf(fmaxf(d, -200.f), 200.f);
                Csum += d;
                A1 = raw1 - d; A2 = raw2 - d;
                if (act) { eS[u^1][j1] = ex2f(A1); eS[u^1][j2] = ex2f(A2); }
                __syncwarp();
            }
        }
        if (act) { eS[1][j1] = A1; eS[1][j2] = A2; }
        __syncwarp();
        if (lane == 0) {
            float m = -3.4e38f;
            #pragma unroll
            for (int p = 0; p < NK; ++p) {
                float te = trans[SEND*NK + p];
                if (p == SEND) te = NEGV;
                m = fmaxf(m, eS[1][p] + te * L2E);
            }
            float s = 0.f;
            #pragma unroll
            for (int p = 0; p < NK; ++p) {
                float te = trans[SEND*NK + p];
                if (p == SEND) te = NEGV;
                s += ex2f(eS[1][p] + te * L2E - m);
            }
            out[b] = (m + lg2f(s) + Csum) * LN2F;
        }
    }
}

extern "C" void kernel_launch(void* const* d_in, const int* in_sizes, int n_in,
                              void* d_out, int out_size)
{
    const float* feats = (const float*)d_in[0];
    const float* trans = (const float*)d_in[1];
    float* out = (float*)d_out;
    cudaFuncSetAttribute(crf_kernel, cudaFuncAttributeMaxDynamicSharedMemorySize,
                         SMEM_BYTES);
    cudaFuncSetAttribute(crf_kernel, cudaFuncAttributePreferredSharedMemoryCarveout,
                         100);
    crf_kernel<<<NB/4, 256, SMEM_BYTES>>>(feats, trans, out);
}